// round 13
// baseline (speedup 1.0000x reference)
#include <cuda_runtime.h>

#define NTOT 4096
#define CDIM 256

// ---- output layout ----
#define OFF_SS 2097152ll                  // 2*256*4096
#define OFF_SC 35651584ll                 // OFF_SS + 2*4096*4096

// ---- scratch ----
__device__ float g_P[6 * 2 * 64 * NTOT];   // P[proj][b][o][n]
__device__ float g_feat[4 * 64 * NTOT];    // feats [brb][o][m]
__device__ float g_rowsum[4 * NTOT];

// ---- packed f32x2 helpers ----
typedef unsigned long long ull;
__device__ __forceinline__ ull pk2(float lo, float hi) {
    ull r; asm("mov.b64 %0, {%1,%2};" : "=l"(r) : "f"(lo), "f"(hi)); return r;
}
__device__ __forceinline__ void fma2(ull& d, ull a, ull b) {
    asm("fma.rn.f32x2 %0, %1, %2, %0;" : "+l"(d) : "l"(a), "l"(b));
}
__device__ __forceinline__ float2 upk(ull v) {
    float2 f; asm("mov.b64 {%0,%1}, %2;" : "=f"(f.x), "=f"(f.y) : "l"(v)); return f;
}

// =====================================================================
// Kernel 1: projections. P[proj][b][o][n] = sum_c W[o][c] * src[b][c][n]
// =====================================================================
__global__ __launch_bounds__(256) void proj_kernel(
    const float* __restrict__ x, const float* __restrict__ mask,
    const float* __restrict__ w0, const float* __restrict__ w1,
    const float* __restrict__ w2, const float* __restrict__ w3,
    const float* __restrict__ w4, const float* __restrict__ w5) {
    __shared__ float Wsm[64][68];
    __shared__ float Xsm[64][68];
    int nt = blockIdx.x, proj = blockIdx.y, b = blockIdx.z;
    int n0 = nt * 64;
    const float* W = (proj == 0) ? w0 : (proj == 1) ? w1 : (proj == 2) ? w2
                   : (proj == 3) ? w3 : (proj == 4) ? w4 : w5;
    bool usefg = (proj == 0 || proj == 1 || proj == 2 || proj == 4);
    int t = threadIdx.x;
    int ty = t >> 4, tx = t & 15;

    float mv = mask[b * NTOT + n0 + (t & 63)];
    float fac = usefg ? mv : (1.0f - mv);

    ull acc2[4][2] = {};
    for (int ct = 0; ct < 4; ct++) {
        __syncthreads();
        #pragma unroll
        for (int pass = 0; pass < 16; pass++) {
            int cc = t & 63;
            int o = (pass << 2) + (t >> 6);
            Wsm[cc][o] = W[o * CDIM + ct * 64 + cc];
        }
        #pragma unroll
        for (int pass = 0; pass < 16; pass++) {
            int nn = t & 63;
            int cc = (pass << 2) + (t >> 6);
            Xsm[cc][nn] = x[((size_t)b * CDIM + ct * 64 + cc) * NTOT + n0 + nn] * fac;
        }
        __syncthreads();
        #pragma unroll 8
        for (int cc = 0; cc < 64; cc++) {
            float4 a = *(const float4*)&Wsm[cc][ty << 2];
            float4 v = *(const float4*)&Xsm[cc][tx << 2];
            ull v01 = pk2(v.x, v.y), v23 = pk2(v.z, v.w);
            ull a0 = pk2(a.x, a.x); fma2(acc2[0][0], a0, v01); fma2(acc2[0][1], a0, v23);
            ull a1 = pk2(a.y, a.y); fma2(acc2[1][0], a1, v01); fma2(acc2[1][1], a1, v23);
            ull a2 = pk2(a.z, a.z); fma2(acc2[2][0], a2, v01); fma2(acc2[2][1], a2, v23);
            ull a3 = pk2(a.w, a.w); fma2(acc2[3][0], a3, v01); fma2(acc2[3][1], a3, v23);
        }
    }
    float* Pout = &g_P[(size_t)((proj * 2 + b) * 64) * NTOT];
    #pragma unroll
    for (int i = 0; i < 4; i++) {
        float2 p0 = upk(acc2[i][0]), p1 = upk(acc2[i][1]);
        float4 o4 = make_float4(p0.x, p0.y, p1.x, p1.y);
        *(float4*)&Pout[(size_t)((ty << 2) + i) * NTOT + n0 + (tx << 2)] = o4;
    }
}

// =====================================================================
// Kernel 2: scorefeat. Per CTA: m-block of 128 rows, stream n in 128 tiles.
//  phase A: S-tile = Q^T K (8x8/thread), e = exp(S) -> global + e_sm,
//           row sums in regs
//  phase B: feat_acc[8m][4o] += e_sm * V  (contract n)
//  end: reduce row sums once, scale feat by 1/rowsum, write feat.
// =====================================================================
__global__ __launch_bounds__(256) void scorefeat_kernel(float* __restrict__ out) {
    extern __shared__ float sm[];
    float* Qsm  = sm;              // [64][128]   8192
    float* Ksm  = sm + 8192;       // [64][128]   8192
    float* Vsm  = sm + 16384;      // [128 nn][68 o]  8704
    float* esm  = sm + 25088;      // [128 m][132 n]  16896
    float* redS = sm + 41984;      // [128][16]   2048
    float* sInvA = sm + 44032;     // [128]
    int mt = blockIdx.x, br = blockIdx.y, b = blockIdx.z;
    int brb = br * 2 + b;
    int m0 = mt * 128;
    const float* Q = &g_P[(size_t)((((br == 0) ? 1 : 4) * 2 + b) * 64) * NTOT];
    const float* K = &g_P[(size_t)((((br == 0) ? 0 : 3) * 2 + b) * 64) * NTOT];
    const float* V = &g_P[(size_t)((((br == 0) ? 2 : 5) * 2 + b) * 64) * NTOT];
    float* S = out + (br ? OFF_SC : OFF_SS) + (size_t)b * NTOT * NTOT;
    int t = threadIdx.x, tx = t & 15, ty = t >> 4;

    #pragma unroll
    for (int p = 0; p < 8; p++) {
        int c = p * 256 + t;
        int o = c >> 5, moff = (c & 31) << 2;
        *(float4*)&Qsm[o * 128 + moff] = *(const float4*)&Q[(size_t)o * NTOT + m0 + moff];
    }

    float rsum[8];
    #pragma unroll
    for (int i = 0; i < 8; i++) rsum[i] = 0.0f;
    ull facc[8][2] = {};   // [8 m][4 o packed]

    for (int nt = 0; nt < 32; nt++) {
        int n0 = nt * 128;
        __syncthreads();   // prev feat reads of Ksm/Vsm/esm done
        #pragma unroll
        for (int p = 0; p < 8; p++) {
            int c = p * 256 + t;
            int o = c >> 5, noff = (c & 31) << 2;
            *(float4*)&Ksm[o * 128 + noff] = *(const float4*)&K[(size_t)o * NTOT + n0 + noff];
        }
        #pragma unroll
        for (int p = 0; p < 32; p++) {
            int c = p * 256 + t;
            int o = c >> 7, nn = c & 127;
            Vsm[nn * 68 + o] = V[(size_t)o * NTOT + n0 + nn];
        }
        __syncthreads();

        // ---- phase A: score GEMM ----
        ull acc[2][4][4] = {};
        #pragma unroll 4
        for (int o = 0; o < 64; o++) {
            float4 a0 = *(const float4*)&Qsm[o * 128 + (ty << 2)];
            float4 a1 = *(const float4*)&Qsm[o * 128 + 64 + (ty << 2)];
            float4 b0 = *(const float4*)&Ksm[o * 128 + (tx << 2)];
            float4 b1 = *(const float4*)&Ksm[o * 128 + 64 + (tx << 2)];
            ull bp0 = pk2(b0.x, b0.y), bp1 = pk2(b0.z, b0.w);
            ull bp2 = pk2(b1.x, b1.y), bp3 = pk2(b1.z, b1.w);
            float av0[4] = {a0.x, a0.y, a0.z, a0.w};
            float av1[4] = {a1.x, a1.y, a1.z, a1.w};
            #pragma unroll
            for (int i = 0; i < 4; i++) {
                ull ap = pk2(av0[i], av0[i]);
                fma2(acc[0][i][0], ap, bp0); fma2(acc[0][i][1], ap, bp1);
                fma2(acc[0][i][2], ap, bp2); fma2(acc[0][i][3], ap, bp3);
            }
            #pragma unroll
            for (int i = 0; i < 4; i++) {
                ull ap = pk2(av1[i], av1[i]);
                fma2(acc[1][i][0], ap, bp0); fma2(acc[1][i][1], ap, bp1);
                fma2(acc[1][i][2], ap, bp2); fma2(acc[1][i][3], ap, bp3);
            }
        }

        // ---- epilogue: exp, store e (global + smem), row sums ----
        #pragma unroll
        for (int mh = 0; mh < 2; mh++)
            #pragma unroll
            for (int i = 0; i < 4; i++) {
                int row = mh * 64 + (ty << 2) + i;
                float2 p0 = upk(acc[mh][i][0]), p1 = upk(acc[mh][i][1]);
                float2 p2 = upk(acc[mh][i][2]), p3 = upk(acc[mh][i][3]);
                float e0 = __expf(p0.x), e1 = __expf(p0.y);
                float e2 = __expf(p1.x), e3 = __expf(p1.y);
                float e4 = __expf(p2.x), e5 = __expf(p2.y);
                float e6 = __expf(p3.x), e7 = __expf(p3.y);
                size_t base = (size_t)(m0 + row) * NTOT + n0;
                float4 q0 = make_float4(e0, e1, e2, e3);
                float4 q1 = make_float4(e4, e5, e6, e7);
                *(float4*)&S[base + (tx << 2)] = q0;
                *(float4*)&S[base + 64 + (tx << 2)] = q1;
                *(float4*)&esm[row * 132 + (tx << 2)] = q0;
                *(float4*)&esm[row * 132 + 64 + (tx << 2)] = q1;
                rsum[mh * 4 + i] += ((e0 + e1) + (e2 + e3)) + ((e4 + e5) + (e6 + e7));
            }
        __syncthreads();

        // ---- phase B: feat GEMM, contract nn over this tile ----
        #pragma unroll 2
        for (int nn2 = 0; nn2 < 64; nn2++) {
            int nn = nn2 << 1;
            float4 v0 = *(const float4*)&Vsm[nn * 68 + (tx << 2)];
            float4 v1 = *(const float4*)&Vsm[(nn + 1) * 68 + (tx << 2)];
            ull bp0 = pk2(v0.x, v0.y), bp1 = pk2(v0.z, v0.w);
            ull cp0 = pk2(v1.x, v1.y), cp1 = pk2(v1.z, v1.w);
            float2 a2[8];
            #pragma unroll
            for (int i = 0; i < 8; i++) {
                int row = (i < 4) ? ((ty << 2) + i) : (64 + (ty << 2) + (i - 4));
                a2[i] = *(const float2*)&esm[row * 132 + nn];
            }
            #pragma unroll
            for (int i = 0; i < 8; i++) {
                ull ap0 = pk2(a2[i].x, a2[i].x);
                fma2(facc[i][0], ap0, bp0); fma2(facc[i][1], ap0, bp1);
                ull ap1 = pk2(a2[i].y, a2[i].y);
                fma2(facc[i][0], ap1, cp0); fma2(facc[i][1], ap1, cp1);
            }
        }
    }

    // ---- final: rowsum reduce, inv, scale + write feat ----
    __syncthreads();
    #pragma unroll
    for (int mh = 0; mh < 2; mh++)
        #pragma unroll
        for (int i = 0; i < 4; i++)
            redS[(mh * 64 + (ty << 2) + i) * 16 + tx] = rsum[mh * 4 + i];
    __syncthreads();
    if (t < 128) {
        float s = redS[t * 16];
        #pragma unroll
        for (int j = 1; j < 16; j++) s += redS[t * 16 + j];
        g_rowsum[brb * NTOT + m0 + t] = s;
        sInvA[t] = 1.0f / s;
    }
    __syncthreads();
    // stage scaled feat into esm[o][m] (o<64 rows), then coalesced write
    #pragma unroll
    for (int i = 0; i < 8; i++) {
        int row = (i < 4) ? ((ty << 2) + i) : (64 + (ty << 2) + (i - 4));
        float iv = sInvA[row];
        float2 f0 = upk(facc[i][0]), f1 = upk(facc[i][1]);
        int o0 = tx << 2;
        esm[o0 * 132 + row] = f0.x * iv;
        esm[(o0 + 1) * 132 + row] = f0.y * iv;
        esm[(o0 + 2) * 132 + row] = f1.x * iv;
        esm[(o0 + 3) * 132 + row] = f1.y * iv;
    }
    __syncthreads();
    float* F = &g_feat[(size_t)(brb * 64) * NTOT];
    #pragma unroll
    for (int p = 0; p < 32; p++) {
        int c = p * 256 + t;
        int o = c >> 7, m = c & 127;
        F[(size_t)o * NTOT + m0 + m] = esm[o * 132 + m];
    }
}

// =====================================================================
// Kernel 3: scale. p = e * inv(rowsum). Pure bandwidth pass.
// grid (4 segs, 4096 rows, 4 brb), 256 threads, float4 each.
// =====================================================================
__global__ __launch_bounds__(256) void scale_kernel(float* __restrict__ out) {
    int brb = blockIdx.z, row = blockIdx.y, seg = blockIdx.x;
    int br = brb >> 1, b = brb & 1;
    float inv = 1.0f / __ldg(&g_rowsum[brb * NTOT + row]);
    float* S = out + (br ? OFF_SC : OFF_SS) + (size_t)b * NTOT * NTOT;
    size_t base = (size_t)row * NTOT + seg * 1024 + (threadIdx.x << 2);
    float4 e = *(const float4*)&S[base];
    *(float4*)&S[base] = make_float4(e.x * inv, e.y * inv, e.z * inv, e.w * inv);
}

// =====================================================================
// Kernel 4: combine. out = x + w_out * (feat_self + feat_cross)
// =====================================================================
__global__ __launch_bounds__(256) void combine_kernel(
    const float* __restrict__ x, const float* __restrict__ w_out,
    float* __restrict__ out) {
    __shared__ float Wsm[64][68];
    __shared__ float Fsm[64][68];
    int nt = blockIdx.x, ct = blockIdx.y, b = blockIdx.z;
    int n0 = nt * 64, c0 = ct * 64;
    int t = threadIdx.x, ty = t >> 4, tx = t & 15;
    #pragma unroll
    for (int pass = 0; pass < 16; pass++) {
        int o = t & 63;
        int cc = (pass << 2) + (t >> 6);
        Wsm[o][cc] = w_out[(c0 + cc) * 64 + o];
    }
    #pragma unroll
    for (int pass = 0; pass < 16; pass++) {
        int o = (pass << 2) + (t >> 6);
        int nn = t & 63;
        Fsm[o][nn] = g_feat[(size_t)((0 * 2 + b) * 64 + o) * NTOT + n0 + nn]
                   + g_feat[(size_t)((1 * 2 + b) * 64 + o) * NTOT + n0 + nn];
    }
    __syncthreads();
    ull acc2[4][2] = {};
    #pragma unroll 8
    for (int o = 0; o < 64; o++) {
        float4 a = *(const float4*)&Wsm[o][ty << 2];
        float4 v = *(const float4*)&Fsm[o][tx << 2];
        ull v01 = pk2(v.x, v.y), v23 = pk2(v.z, v.w);
        ull a0 = pk2(a.x, a.x); fma2(acc2[0][0], a0, v01); fma2(acc2[0][1], a0, v23);
        ull a1 = pk2(a.y, a.y); fma2(acc2[1][0], a1, v01); fma2(acc2[1][1], a1, v23);
        ull a2 = pk2(a.z, a.z); fma2(acc2[2][0], a2, v01); fma2(acc2[2][1], a2, v23);
        ull a3 = pk2(a.w, a.w); fma2(acc2[3][0], a3, v01); fma2(acc2[3][1], a3, v23);
    }
    #pragma unroll
    for (int i = 0; i < 4; i++) {
        size_t gi = ((size_t)b * CDIM + c0 + (ty << 2) + i) * NTOT + n0 + (tx << 2);
        float4 xv = *(const float4*)&x[gi];
        float2 p0 = upk(acc2[i][0]), p1 = upk(acc2[i][1]);
        *(float4*)&out[gi] = make_float4(xv.x + p0.x, xv.y + p0.y,
                                         xv.z + p1.x, xv.w + p1.y);
    }
}

extern "C" void kernel_launch(void* const* d_in, const int* in_sizes, int n_in,
                              void* d_out, int out_size) {
    const float* x    = (const float*)d_in[0];
    const float* mask = (const float*)d_in[1];
    const float* w_theta_s = (const float*)d_in[2];
    const float* w_phi_s   = (const float*)d_in[3];
    const float* w_gate_s  = (const float*)d_in[4];
    const float* w_theta_c = (const float*)d_in[5];
    const float* w_phi_c   = (const float*)d_in[6];
    const float* w_gate_c  = (const float*)d_in[7];
    const float* w_out     = (const float*)d_in[8];
    float* out = (float*)d_out;

    static int configured = 0;
    if (!configured) {
        cudaFuncSetAttribute(scorefeat_kernel,
            cudaFuncAttributeMaxDynamicSharedMemorySize, 176640);
        configured = 1;
    }

    dim3 g1(64, 6, 2);
    proj_kernel<<<g1, 256>>>(x, mask, w_theta_s, w_phi_s, w_gate_s,
                             w_theta_c, w_phi_c, w_gate_c);
    dim3 g2(32, 2, 2);
    scorefeat_kernel<<<g2, 256, 176640>>>(out);
    dim3 g3(4, 4096, 4);
    scale_kernel<<<g3, 256>>>(out);
    dim3 g4(64, 4, 2);
    combine_kernel<<<g4, 256>>>(x, w_out, out);
}

// round 17
// speedup vs baseline: 2.8382x; 2.8382x over previous
#include <cuda_runtime.h>
#include <cstdint>

#define NTOT 4096
#define CDIM 256
#define OFF_SS 2097152ll
#define OFF_SC 35651584ll
#define INV4096 0.000244140625f

// ---- scratch ----
__device__ int   g_posP[2 * NTOT];   // fg: rank ; bg: -(rank+1)
__device__ int   g_cnt[2];           // Nf per batch
__device__ float g_Qs[4ll * 64 * NTOT];   // compact [brb][o][j]
__device__ float g_Ks[4ll * 64 * NTOT];
__device__ float g_Vs[4ll * 64 * NTOT];
__device__ float g_Eself[2ll * NTOT * NTOT];
__device__ float g_Ecross[2ll * NTOT * NTOT];
__device__ float g_featc[4ll * 64 * NTOT]; // compact feat [brb][o][j]
__device__ float g_feat[4ll * 64 * NTOT];  // full feat [brb][o][m]
__device__ float g_rsc[4 * NTOT];          // compact row sums
__device__ float g_vsum[4 * 64];

typedef unsigned long long ull;
__device__ __forceinline__ ull pk2(float lo, float hi) {
    ull r; asm("mov.b64 %0, {%1,%2};" : "=l"(r) : "f"(lo), "f"(hi)); return r;
}
__device__ __forceinline__ void fma2(ull& d, ull a, ull b) {
    asm("fma.rn.f32x2 %0, %1, %2, %0;" : "+l"(d) : "l"(a), "l"(b));
}
__device__ __forceinline__ float2 upk(ull v) {
    float2 f; asm("mov.b64 {%0,%1}, %2;" : "=f"(f.x), "=f"(f.y) : "l"(v)); return f;
}

// =====================================================================
// Kernel 0: scan -> g_posP, g_cnt
// =====================================================================
__global__ __launch_bounds__(1024) void scan_kernel(const float* __restrict__ mask) {
    __shared__ int ws[32];
    int b = blockIdx.x, t = threadIdx.x;
    int n0 = t * 4;
    int c[4];
    #pragma unroll
    for (int k = 0; k < 4; k++)
        c[k] = (mask[b * NTOT + n0 + k] > 0.5f) ? 1 : 0;
    int tot = c[0] + c[1] + c[2] + c[3];
    int lane = t & 31, w = t >> 5;
    int incl = tot;
    #pragma unroll
    for (int d = 1; d < 32; d <<= 1) {
        int v = __shfl_up_sync(0xffffffffu, incl, d);
        if (lane >= d) incl += v;
    }
    if (lane == 31) ws[w] = incl;
    __syncthreads();
    if (t < 32) {
        int vi = ws[t];
        #pragma unroll
        for (int d = 1; d < 32; d <<= 1) {
            int u = __shfl_up_sync(0xffffffffu, vi, d);
            if (t >= d) vi += u;
        }
        ws[t] = vi;
    }
    __syncthreads();
    int warpoff = (w > 0) ? ws[w - 1] : 0;
    int run = warpoff + incl - tot;   // exclusive prefix of fg count
    #pragma unroll
    for (int k = 0; k < 4; k++) {
        int n = n0 + k;
        g_posP[b * NTOT + n] = c[k] ? run : (-(n - run) - 1);
        run += c[k];
    }
    if (t == 1023) g_cnt[b] = run;
}

// =====================================================================
// Kernel 1: projections, scatter-compacted outputs.
// roles: K=theta, Q=phi, V=gate; fg source for all except proj 3,5 (bg).
// =====================================================================
__global__ __launch_bounds__(256) void proj_kernel(
    const float* __restrict__ x, const float* __restrict__ mask,
    const float* __restrict__ w0, const float* __restrict__ w1,
    const float* __restrict__ w2, const float* __restrict__ w3,
    const float* __restrict__ w4, const float* __restrict__ w5) {
    __shared__ float Wsm[64][68];
    __shared__ float Xsm[64][68];
    int nt = blockIdx.x, proj = blockIdx.y, b = blockIdx.z;
    int n0 = nt * 64;
    const float* W = (proj == 0) ? w0 : (proj == 1) ? w1 : (proj == 2) ? w2
                   : (proj == 3) ? w3 : (proj == 4) ? w4 : w5;
    bool usefg = (proj != 3 && proj != 5);
    int t = threadIdx.x, ty = t >> 4, tx = t & 15;
    float mv = mask[b * NTOT + n0 + (t & 63)];
    float fac = usefg ? mv : (1.0f - mv);

    ull acc2[4][2] = {};
    for (int ct = 0; ct < 4; ct++) {
        __syncthreads();
        #pragma unroll
        for (int pass = 0; pass < 16; pass++) {
            int cc = t & 63, o = (pass << 2) + (t >> 6);
            Wsm[cc][o] = W[o * CDIM + ct * 64 + cc];
        }
        #pragma unroll
        for (int pass = 0; pass < 16; pass++) {
            int nn = t & 63, cc = (pass << 2) + (t >> 6);
            Xsm[cc][nn] = x[((size_t)b * CDIM + ct * 64 + cc) * NTOT + n0 + nn] * fac;
        }
        __syncthreads();
        #pragma unroll 8
        for (int cc = 0; cc < 64; cc++) {
            float4 a = *(const float4*)&Wsm[cc][ty << 2];
            float4 v = *(const float4*)&Xsm[cc][tx << 2];
            ull v01 = pk2(v.x, v.y), v23 = pk2(v.z, v.w);
            ull a0 = pk2(a.x, a.x); fma2(acc2[0][0], a0, v01); fma2(acc2[0][1], a0, v23);
            ull a1 = pk2(a.y, a.y); fma2(acc2[1][0], a1, v01); fma2(acc2[1][1], a1, v23);
            ull a2 = pk2(a.z, a.z); fma2(acc2[2][0], a2, v01); fma2(acc2[2][1], a2, v23);
            ull a3 = pk2(a.w, a.w); fma2(acc2[3][0], a3, v01); fma2(acc2[3][1], a3, v23);
        }
    }

    int role = (proj == 0 || proj == 3) ? 0 : (proj == 1 || proj == 4) ? 1 : 2;
    int brb = ((proj >= 3) ? 1 : 0) * 2 + b;
    float* dst = ((role == 0) ? g_Ks : (role == 1) ? g_Qs : g_Vs)
               + (size_t)brb * 64 * NTOT;
    int pp[4];
    #pragma unroll
    for (int jj = 0; jj < 4; jj++)
        pp[jj] = g_posP[b * NTOT + n0 + (tx << 2) + jj];

    #pragma unroll
    for (int i = 0; i < 4; i++) {
        int o = (ty << 2) + i;
        float2 p0 = upk(acc2[i][0]), p1 = upk(acc2[i][1]);
        float vv[4] = {p0.x, p0.y, p1.x, p1.y};
        #pragma unroll
        for (int jj = 0; jj < 4; jj++) {
            bool isfg = pp[jj] >= 0;
            if (isfg == usefg) {
                int pos = isfg ? pp[jj] : (-pp[jj] - 1);
                dst[(size_t)o * NTOT + pos] = vv[jj];
            }
        }
    }
}

// =====================================================================
// Kernel 2: vsum. g_vsum[brb][o] = sum_j V[brb][o][j], j < Nc
// =====================================================================
__global__ __launch_bounds__(128) void vsum_kernel() {
    int o = blockIdx.x, brb = blockIdx.y;
    int b = brb & 1, br = brb >> 1;
    int Nf = g_cnt[b];
    int Nc = br ? (NTOT - Nf) : Nf;
    const float* V = g_Vs + ((size_t)brb * 64 + o) * NTOT;
    int t = threadIdx.x;
    float s = 0.0f;
    for (int j = t; j < Nc; j += 128) s += V[j];
    #pragma unroll
    for (int d = 16; d > 0; d >>= 1) s += __shfl_down_sync(0xffffffffu, s, d);
    __shared__ float red[4];
    if ((t & 31) == 0) red[t >> 5] = s;
    __syncthreads();
    if (t == 0) g_vsum[brb * 64 + o] = red[0] + red[1] + red[2] + red[3];
}

// =====================================================================
// Kernel 3: scorefeat_compact. 64 fg rows per CTA, stream Nc cols in 128s.
// Grid covers ALL 4096 possible query rows (64 m-tiles); m0 >= Nf -> return.
// =====================================================================
__global__ __launch_bounds__(256) void scorefeat_kernel() {
    extern __shared__ float sm[];
    float* Qsm  = sm;          // [64][68]
    float* Ksm  = sm + 4352;   // [64][132]
    float* Vsm  = sm + 12800;  // [128][68]
    float* esm  = sm + 21504;  // [64][132]
    float* redS = sm + 29952;  // [64][17]
    int mt = blockIdx.x, brb = blockIdx.y;
    int b = brb & 1, br = brb >> 1;
    int Nf = g_cnt[b];
    int m0 = mt * 64;
    if (m0 >= Nf) return;
    int Nc = br ? (NTOT - Nf) : Nf;
    int ntiles = (Nc + 127) >> 7;
    const float* Q = g_Qs + (size_t)brb * 64 * NTOT;
    const float* K = g_Ks + (size_t)brb * 64 * NTOT;
    const float* V = g_Vs + (size_t)brb * 64 * NTOT;
    float* E = (br ? g_Ecross : g_Eself) + (size_t)b * NTOT * NTOT;
    int t = threadIdx.x, tx = t & 15, ty = t >> 4;

    #pragma unroll
    for (int p = 0; p < 4; p++) {
        int c = p * 256 + t;
        int o = c >> 4, moff = (c & 15) << 2;
        *(float4*)&Qsm[o * 68 + moff] = *(const float4*)&Q[(size_t)o * NTOT + m0 + moff];
    }

    float rsum[4] = {0.0f, 0.0f, 0.0f, 0.0f};
    ull facc[4][2] = {};

    for (int nt = 0; nt < ntiles; nt++) {
        int n0 = nt * 128;
        __syncthreads();
        #pragma unroll
        for (int p = 0; p < 8; p++) {
            int c = p * 256 + t;
            int o = c >> 5, noff = (c & 31) << 2;
            *(float4*)&Ksm[o * 132 + noff] = *(const float4*)&K[(size_t)o * NTOT + n0 + noff];
        }
        #pragma unroll
        for (int p = 0; p < 32; p++) {
            int c = p * 256 + t;
            int o = c >> 7, nn = c & 127;
            Vsm[nn * 68 + o] = V[(size_t)o * NTOT + n0 + nn];
        }
        __syncthreads();

        // phase A
        ull acc[4][4] = {};
        #pragma unroll 4
        for (int o = 0; o < 64; o++) {
            float4 a = *(const float4*)&Qsm[o * 68 + (ty << 2)];
            float4 b0 = *(const float4*)&Ksm[o * 132 + (tx << 2)];
            float4 b1 = *(const float4*)&Ksm[o * 132 + 64 + (tx << 2)];
            ull bp0 = pk2(b0.x, b0.y), bp1 = pk2(b0.z, b0.w);
            ull bp2 = pk2(b1.x, b1.y), bp3 = pk2(b1.z, b1.w);
            float av[4] = {a.x, a.y, a.z, a.w};
            #pragma unroll
            for (int i = 0; i < 4; i++) {
                ull ap = pk2(av[i], av[i]);
                fma2(acc[i][0], ap, bp0); fma2(acc[i][1], ap, bp1);
                fma2(acc[i][2], ap, bp2); fma2(acc[i][3], ap, bp3);
            }
        }

        // epilogue: masked exp, store E + esm, row sums
        int j0 = n0 + (tx << 2), j1 = j0 + 64;
        #pragma unroll
        for (int i = 0; i < 4; i++) {
            int row = (ty << 2) + i;
            float2 p0 = upk(acc[i][0]), p1 = upk(acc[i][1]);
            float2 p2 = upk(acc[i][2]), p3 = upk(acc[i][3]);
            float e0 = (j0 + 0 < Nc) ? __expf(p0.x) : 0.0f;
            float e1 = (j0 + 1 < Nc) ? __expf(p0.y) : 0.0f;
            float e2 = (j0 + 2 < Nc) ? __expf(p1.x) : 0.0f;
            float e3 = (j0 + 3 < Nc) ? __expf(p1.y) : 0.0f;
            float e4 = (j1 + 0 < Nc) ? __expf(p2.x) : 0.0f;
            float e5 = (j1 + 1 < Nc) ? __expf(p2.y) : 0.0f;
            float e6 = (j1 + 2 < Nc) ? __expf(p3.x) : 0.0f;
            float e7 = (j1 + 3 < Nc) ? __expf(p3.y) : 0.0f;
            rsum[i] += ((e0 + e1) + (e2 + e3)) + ((e4 + e5) + (e6 + e7));
            size_t gb = (size_t)(m0 + row) * NTOT;
            *(float4*)&E[gb + j0] = make_float4(e0, e1, e2, e3);
            *(float4*)&E[gb + j1] = make_float4(e4, e5, e6, e7);
            *(float4*)&esm[row * 132 + (tx << 2)] = make_float4(e0, e1, e2, e3);
            *(float4*)&esm[row * 132 + 64 + (tx << 2)] = make_float4(e4, e5, e6, e7);
        }
        __syncthreads();

        // phase B
        #pragma unroll 2
        for (int nn2 = 0; nn2 < 64; nn2++) {
            int nn = nn2 << 1;
            float4 v0 = *(const float4*)&Vsm[nn * 68 + (tx << 2)];
            float4 v1 = *(const float4*)&Vsm[(nn + 1) * 68 + (tx << 2)];
            ull bp0 = pk2(v0.x, v0.y), bp1 = pk2(v0.z, v0.w);
            ull cp0 = pk2(v1.x, v1.y), cp1 = pk2(v1.z, v1.w);
            float2 a2[4];
            #pragma unroll
            for (int i = 0; i < 4; i++)
                a2[i] = *(const float2*)&esm[((ty << 2) + i) * 132 + nn];
            #pragma unroll
            for (int i = 0; i < 4; i++) {
                ull ap0 = pk2(a2[i].x, a2[i].x);
                fma2(facc[i][0], ap0, bp0); fma2(facc[i][1], ap0, bp1);
                ull ap1 = pk2(a2[i].y, a2[i].y);
                fma2(facc[i][0], ap1, cp0); fma2(facc[i][1], ap1, cp1);
            }
        }
    }

    __syncthreads();
    #pragma unroll
    for (int i = 0; i < 4; i++) redS[((ty << 2) + i) * 17 + tx] = rsum[i];
    __syncthreads();
    if (t < 64) {
        float s = redS[t * 17];
        #pragma unroll
        for (int j = 1; j < 16; j++) s += redS[t * 17 + j];
        g_rsc[brb * NTOT + m0 + t] = s;
    }
    float* Fc = g_featc + (size_t)brb * 64 * NTOT;
    #pragma unroll
    for (int i = 0; i < 4; i++) {
        int row = m0 + (ty << 2) + i;
        float2 f0 = upk(facc[i][0]), f1 = upk(facc[i][1]);
        int o0 = tx << 2;
        Fc[(size_t)o0 * NTOT + row] = f0.x;
        Fc[(size_t)(o0 + 1) * NTOT + row] = f0.y;
        Fc[(size_t)(o0 + 2) * NTOT + row] = f1.x;
        Fc[(size_t)(o0 + 3) * NTOT + row] = f1.y;
    }
}

// =====================================================================
// Kernel 4: featfix. Full feat[brb][o][m] from compact + constants.
// =====================================================================
__global__ __launch_bounds__(256) void featfix_kernel() {
    int m = blockIdx.x * 256 + threadIdx.x;
    int brb = blockIdx.y;
    int b = brb & 1;
    int p = g_posP[b * NTOT + m];
    float* F = g_feat + (size_t)brb * 64 * NTOT + m;
    if (p >= 0) {
        int Nf = g_cnt[b];
        int Nc = (brb >> 1) ? (NTOT - Nf) : Nf;
        float inv = 1.0f / (g_rsc[brb * NTOT + p] + (float)(NTOT - Nc));
        const float* Fc = g_featc + (size_t)brb * 64 * NTOT + p;
        #pragma unroll 8
        for (int o = 0; o < 64; o++)
            F[(size_t)o * NTOT] = Fc[(size_t)o * NTOT] * inv;
    } else {
        #pragma unroll 8
        for (int o = 0; o < 64; o++)
            F[(size_t)o * NTOT] = g_vsum[brb * 64 + o] * INV4096;
    }
}

// =====================================================================
// Kernel 5: expand. Full softmax matrices from compact E + inv.
// =====================================================================
__global__ __launch_bounds__(256) void expand_kernel(float* __restrict__ out) {
    int brb = blockIdx.z, row = blockIdx.y, seg = blockIdx.x;
    int b = brb & 1, br = brb >> 1;
    int t = threadIdx.x;
    float* Srow = out + (br ? OFF_SC : OFF_SS) + (size_t)b * NTOT * NTOT
                + (size_t)row * NTOT + seg * 1024 + (t << 2);
    int pr = g_posP[b * NTOT + row];
    if (pr < 0) {
        *(float4*)Srow = make_float4(INV4096, INV4096, INV4096, INV4096);
        return;
    }
    int Nf = g_cnt[b];
    int Nc = br ? (NTOT - Nf) : Nf;
    float inv = 1.0f / (g_rsc[brb * NTOT + pr] + (float)(NTOT - Nc));
    const float* E = (br ? g_Ecross : g_Eself) + (size_t)b * NTOT * NTOT
                   + (size_t)pr * NTOT;
    int4 pp = *(const int4*)&g_posP[b * NTOT + seg * 1024 + (t << 2)];
    int pa[4] = {pp.x, pp.y, pp.z, pp.w};
    float v[4];
    #pragma unroll
    for (int k = 0; k < 4; k++) {
        bool isfg = pa[k] >= 0;
        if (isfg == (br == 0)) {
            int jc = isfg ? pa[k] : (-pa[k] - 1);
            v[k] = E[jc] * inv;
        } else {
            v[k] = inv;
        }
    }
    *(float4*)Srow = make_float4(v[0], v[1], v[2], v[3]);
}

// =====================================================================
// Kernel 6: combine. out = x + w_out * (feat_self + feat_cross)
// =====================================================================
__global__ __launch_bounds__(256) void combine_kernel(
    const float* __restrict__ x, const float* __restrict__ w_out,
    float* __restrict__ out) {
    __shared__ float Wsm[64][68];
    __shared__ float Fsm[64][68];
    int nt = blockIdx.x, ct = blockIdx.y, b = blockIdx.z;
    int n0 = nt * 64, c0 = ct * 64;
    int t = threadIdx.x, ty = t >> 4, tx = t & 15;
    #pragma unroll
    for (int pass = 0; pass < 16; pass++) {
        int o = t & 63, cc = (pass << 2) + (t >> 6);
        Wsm[o][cc] = w_out[(c0 + cc) * 64 + o];
    }
    #pragma unroll
    for (int pass = 0; pass < 16; pass++) {
        int o = (pass << 2) + (t >> 6), nn = t & 63;
        Fsm[o][nn] = g_feat[(size_t)((0 * 2 + b) * 64 + o) * NTOT + n0 + nn]
                   + g_feat[(size_t)((1 * 2 + b) * 64 + o) * NTOT + n0 + nn];
    }
    __syncthreads();
    ull acc2[4][2] = {};
    #pragma unroll 8
    for (int o = 0; o < 64; o++) {
        float4 a = *(const float4*)&Wsm[o][ty << 2];
        float4 v = *(const float4*)&Fsm[o][tx << 2];
        ull v01 = pk2(v.x, v.y), v23 = pk2(v.z, v.w);
        ull a0 = pk2(a.x, a.x); fma2(acc2[0][0], a0, v01); fma2(acc2[0][1], a0, v23);
        ull a1 = pk2(a.y, a.y); fma2(acc2[1][0], a1, v01); fma2(acc2[1][1], a1, v23);
        ull a2 = pk2(a.z, a.z); fma2(acc2[2][0], a2, v01); fma2(acc2[2][1], a2, v23);
        ull a3 = pk2(a.w, a.w); fma2(acc2[3][0], a3, v01); fma2(acc2[3][1], a3, v23);
    }
    #pragma unroll
    for (int i = 0; i < 4; i++) {
        size_t gi = ((size_t)b * CDIM + c0 + (ty << 2) + i) * NTOT + n0 + (tx << 2);
        float4 xv = *(const float4*)&x[gi];
        float2 p0 = upk(acc2[i][0]), p1 = upk(acc2[i][1]);
        *(float4*)&out[gi] = make_float4(xv.x + p0.x, xv.y + p0.y,
                                         xv.z + p1.x, xv.w + p1.y);
    }
}

extern "C" void kernel_launch(void* const* d_in, const int* in_sizes, int n_in,
                              void* d_out, int out_size) {
    const float* x    = (const float*)d_in[0];
    const float* mask = (const float*)d_in[1];
    const float* w_theta_s = (const float*)d_in[2];
    const float* w_phi_s   = (const float*)d_in[3];
    const float* w_gate_s  = (const float*)d_in[4];
    const float* w_theta_c = (const float*)d_in[5];
    const float* w_phi_c   = (const float*)d_in[6];
    const float* w_gate_c  = (const float*)d_in[7];
    const float* w_out     = (const float*)d_in[8];
    float* out = (float*)d_out;

    static int configured = 0;
    if (!configured) {
        cudaFuncSetAttribute(scorefeat_kernel,
            cudaFuncAttributeMaxDynamicSharedMemorySize, 124160);
        configured = 1;
    }

    scan_kernel<<<2, 1024>>>(mask);
    dim3 g1(64, 6, 2);
    proj_kernel<<<g1, 256>>>(x, mask, w_theta_s, w_phi_s, w_gate_s,
                             w_theta_c, w_phi_c, w_gate_c);
    dim3 gv(64, 4);
    vsum_kernel<<<gv, 128>>>();
    dim3 g2(64, 4);   // FIX: full 4096-row coverage (Nf can exceed 2048)
    scorefeat_kernel<<<g2, 256, 124160>>>();
    dim3 gf(16, 4);
    featfix_kernel<<<gf, 256>>>();
    dim3 ge(4, 4096, 4);
    expand_kernel<<<ge, 256>>>(out);
    dim3 g4(64, 4, 2);
    combine_kernel<<<g4, 256>>>(x, w_out, out);
}